// round 1
// baseline (speedup 1.0000x reference)
#include <cuda_runtime.h>
#include <math.h>

#define BATCH 16384
#define HID   256
#define SDIM  4
#define NOBS  16
#define TOUT  16
#define G4H   1024   // 4*HID

// Static device scratch (allowed; no runtime allocation).
// g_h[lstm][pingpong][B*H], lstm: 0=spEnc 1=poEnc 2=spDec 3=crDec
__device__ float g_h[4][2][BATCH * HID];
__device__ float g_c[4][BATCH * HID];
__device__ float g_x[2][BATCH * SDIM];   // decoder feedback inputs: 0=speed, 1=cross

struct StepP {
    const float* Wih[2];
    const float* Whh[2];
    const float* bih[2];
    const float* bhh[2];
    const float* x[2];     // used when x_from_g == 0
    int x_stride, x_off, x_from_g;
    int lstm[2];
    int inb, outb, first;
};

__device__ __forceinline__ float sigf(float v) { return 1.0f / (1.0f + expf(-v)); }

// One LSTM step for two independent LSTMs (blockIdx.z selects).
// gates[B, 4H] = h_in @ Whh^T + x @ Wih^T + bih + bhh, then cell update.
// Block tile: 128 batch rows x 32 hidden units (=> 128 gate columns j, 256+j, 512+j, 768+j).
__global__ __launch_bounds__(256, 2) void lstm_step_kernel(StepP p) {
    const int z = blockIdx.z;
    const int L = p.lstm[z];
    const float* __restrict__ Whh = p.Whh[z];
    const float* __restrict__ Wih = p.Wih[z];
    const float* __restrict__ bih = p.bih[z];
    const float* __restrict__ bhh = p.bhh[z];
    const float* __restrict__ xin = p.x_from_g ? g_x[z] : p.x[z];
    const float* __restrict__ hin = g_h[L][p.inb];
    float* __restrict__ hout = g_h[L][p.outb];
    float* __restrict__ cptr = g_c[L];

    const int m0 = blockIdx.x * 128;   // batch tile origin
    const int j0 = blockIdx.y * 32;    // hidden-unit tile origin
    const int t  = threadIdx.x;        // 256 threads
    const int tx = t & 15;             // 16 threads over hidden (2 j each)
    const int ty = t >> 4;             // 16 threads over batch (8 rows each)

    __shared__ __align__(16) float As[128][16];   // h tile [batch][k]
    __shared__ float Bs[16][128];                 // Whh tile [k][gatecol]
    __shared__ float WihS[128][SDIM];
    __shared__ float biasS[128];
    __shared__ float Xs[128][SDIM];

    if (t < 128) {
        int row = (t >> 5) * HID + j0 + (t & 31);   // Whh/Wih row for gate-col t
        biasS[t] = bih[row] + bhh[row];
        #pragma unroll
        for (int s = 0; s < SDIM; s++) WihS[t][s] = Wih[row * SDIM + s];
    }
    #pragma unroll
    for (int i = 0; i < 2; i++) {
        int e = t + i * 256;              // 512 elems = 128 rows x 4
        int row = e >> 2, s = e & 3;
        Xs[row][s] = xin[(size_t)(m0 + row) * p.x_stride + p.x_off + s];
    }

    float acc[8][8];
    #pragma unroll
    for (int r = 0; r < 8; r++)
        #pragma unroll
        for (int j = 0; j < 8; j++) acc[r][j] = 0.0f;

    if (!p.first) {
        for (int k0 = 0; k0 < HID; k0 += 16) {
            __syncthreads();  // protect previous iter's reads (and orders top loads)
            #pragma unroll
            for (int i = 0; i < 2; i++) {
                int e = t + i * 256;          // 512 float4 = 128 rows x 4
                int row = e >> 2, kq = e & 3;
                float4 v = *reinterpret_cast<const float4*>(
                    &hin[(size_t)(m0 + row) * HID + k0 + kq * 4]);
                *reinterpret_cast<float4*>(&As[row][kq * 4]) = v;
            }
            #pragma unroll
            for (int i = 0; i < 8; i++) {
                int e = t + i * 256;          // 2048 elems
                int c = e >> 4, k = e & 15;
                int row = (c >> 5) * HID + j0 + (c & 31);
                Bs[k][c] = Whh[(size_t)row * HID + k0 + k];
            }
            __syncthreads();
            #pragma unroll
            for (int k = 0; k < 16; k++) {
                float a[8], bv[8];
                #pragma unroll
                for (int r = 0; r < 8; r++) a[r] = As[ty * 8 + r][k];
                #pragma unroll
                for (int j = 0; j < 8; j++) bv[j] = Bs[k][(j >> 1) * 32 + tx * 2 + (j & 1)];
                #pragma unroll
                for (int r = 0; r < 8; r++)
                    #pragma unroll
                    for (int j = 0; j < 8; j++) acc[r][j] += a[r] * bv[j];
            }
        }
    } else {
        __syncthreads();   // make Xs/WihS/biasS visible for epilogue
    }

    // Epilogue: add x@Wih^T + bias, apply LSTM cell.
    #pragma unroll
    for (int r = 0; r < 8; r++) {
        int b = m0 + ty * 8 + r;
        #pragma unroll
        for (int d = 0; d < 2; d++) {
            int jj = tx * 2 + d;
            int j = j0 + jj;
            float pre[4];
            #pragma unroll
            for (int g = 0; g < 4; g++) {
                float v = acc[r][g * 2 + d] + biasS[g * 32 + jj];
                #pragma unroll
                for (int s = 0; s < SDIM; s++) v += Xs[ty * 8 + r][s] * WihS[g * 32 + jj][s];
                pre[g] = v;
            }
            float ig = sigf(pre[0]);
            float fg = sigf(pre[1]);
            float gg = tanhf(pre[2]);
            float og = sigf(pre[3]);
            size_t idx = (size_t)b * HID + j;
            float cold = p.first ? 0.0f : cptr[idx];
            float cn = fg * cold + ig * gg;
            cptr[idx] = cn;
            hout[idx] = og * tanhf(cn);
        }
    }
}

// h0 = h_spEnc + h_poEnc ; c0 likewise -> init both decoders; init feedback x.
__global__ void combine_kernel(const float* __restrict__ speed,
                               const float* __restrict__ pos) {
    const int stride = gridDim.x * blockDim.x;
    for (int i = blockIdx.x * blockDim.x + threadIdx.x; i < BATCH * HID; i += stride) {
        float h0 = g_h[0][0][i] + g_h[1][0][i];
        float c0 = g_c[0][i] + g_c[1][i];
        g_h[2][0][i] = h0;
        g_h[3][0][i] = h0;
        g_c[2][i] = c0;
        g_c[3][i] = c0;
    }
    for (int jx = blockIdx.x * blockDim.x + threadIdx.x; jx < BATCH * SDIM; jx += stride) {
        int b = jx >> 2, s = jx & 3;
        size_t src = (size_t)b * NOBS * SDIM + (NOBS - 1) * SDIM + s;
        g_x[0][jx] = speed[src];
        g_x[1][jx] = pos[src];
    }
}

// Decoder heads: warp per batch row. blockIdx.y: 0 = speed branch, 1 = crossing branch.
__global__ void head_kernel(const float* __restrict__ fcW, const float* __restrict__ fcb,
                            const float* __restrict__ crW, const float* __restrict__ crb,
                            const float* __restrict__ embW, const float* __restrict__ embb,
                            float* __restrict__ out, int t, int hb) {
    const int warp = threadIdx.x >> 5;
    const int lane = threadIdx.x & 31;
    const int b = blockIdx.x * 8 + warp;
    const int br = blockIdx.y;
    const float* h = g_h[2 + br][hb] + (size_t)b * HID;

    float hv[8];
    #pragma unroll
    for (int i = 0; i < 8; i++) hv[i] = h[lane + 32 * i];

    if (br == 0) {
        // speed: out = hardtanh(h @ fcW^T + fcb), feedback = out
        #pragma unroll
        for (int s = 0; s < SDIM; s++) {
            float v = 0.0f;
            #pragma unroll
            for (int i = 0; i < 8; i++) v += hv[i] * fcW[s * HID + lane + 32 * i];
            #pragma unroll
            for (int o = 16; o; o >>= 1) v += __shfl_down_sync(0xffffffffu, v, o);
            if (lane == 0) {
                v += fcb[s];
                v = fminf(fmaxf(v, -100.0f), 100.0f);
                out[(size_t)b * (TOUT * SDIM) + t * SDIM + s] = v;
                g_x[0][b * SDIM + s] = v;
            }
        }
    } else {
        // crossing: softmax(relu(h @ crW^T + crb)); feedback = relu(h @ embW^T + embb)
        float l0 = 0.0f, l1 = 0.0f;
        #pragma unroll
        for (int i = 0; i < 8; i++) {
            l0 += hv[i] * crW[0 * HID + lane + 32 * i];
            l1 += hv[i] * crW[1 * HID + lane + 32 * i];
        }
        #pragma unroll
        for (int o = 16; o; o >>= 1) {
            l0 += __shfl_down_sync(0xffffffffu, l0, o);
            l1 += __shfl_down_sync(0xffffffffu, l1, o);
        }
        if (lane == 0) {
            l0 = fmaxf(l0 + crb[0], 0.0f);
            l1 = fmaxf(l1 + crb[1], 0.0f);
            float m = fmaxf(l0, l1);
            float e0 = expf(l0 - m), e1 = expf(l1 - m);
            float inv = 1.0f / (e0 + e1);
            float* outc = out + (size_t)BATCH * TOUT * SDIM;
            outc[(size_t)b * (TOUT * 2) + t * 2 + 0] = e0 * inv;
            outc[(size_t)b * (TOUT * 2) + t * 2 + 1] = e1 * inv;
        }
        #pragma unroll
        for (int s = 0; s < SDIM; s++) {
            float v = 0.0f;
            #pragma unroll
            for (int i = 0; i < 8; i++) v += hv[i] * embW[s * HID + lane + 32 * i];
            #pragma unroll
            for (int o = 16; o; o >>= 1) v += __shfl_down_sync(0xffffffffu, v, o);
            if (lane == 0) g_x[1][b * SDIM + s] = fmaxf(v + embb[s], 0.0f);
        }
    }
}

extern "C" void kernel_launch(void* const* d_in, const int* in_sizes, int n_in,
                              void* d_out, int out_size) {
    const float* speed      = (const float*)d_in[0];
    const float* pos        = (const float*)d_in[1];
    const float* sp_Wih     = (const float*)d_in[2];
    const float* sp_Whh     = (const float*)d_in[3];
    const float* sp_bih     = (const float*)d_in[4];
    const float* sp_bhh     = (const float*)d_in[5];
    const float* po_Wih     = (const float*)d_in[6];
    const float* po_Whh     = (const float*)d_in[7];
    const float* po_bih     = (const float*)d_in[8];
    const float* po_bhh     = (const float*)d_in[9];
    const float* dsp_Wih    = (const float*)d_in[10];
    const float* dsp_Whh    = (const float*)d_in[11];
    const float* dsp_bih    = (const float*)d_in[12];
    const float* dsp_bhh    = (const float*)d_in[13];
    const float* dcr_Wih    = (const float*)d_in[14];
    const float* dcr_Whh    = (const float*)d_in[15];
    const float* dcr_bih    = (const float*)d_in[16];
    const float* dcr_bhh    = (const float*)d_in[17];
    const float* fc_speed_W = (const float*)d_in[18];
    const float* fc_speed_b = (const float*)d_in[19];
    const float* fc_cross_W = (const float*)d_in[20];
    const float* fc_cross_b = (const float*)d_in[21];
    const float* emb_W      = (const float*)d_in[22];
    const float* emb_b      = (const float*)d_in[23];
    float* out = (float*)d_out;

    dim3 grid(BATCH / 128, G4H / 128, 2);   // 128 x 8 x 2

    // ---- Encoders: speed (z=0) and pos (z=1) run in the same launches ----
    for (int t = 0; t < NOBS; t++) {
        StepP p{};
        p.Wih[0] = sp_Wih; p.Wih[1] = po_Wih;
        p.Whh[0] = sp_Whh; p.Whh[1] = po_Whh;
        p.bih[0] = sp_bih; p.bih[1] = po_bih;
        p.bhh[0] = sp_bhh; p.bhh[1] = po_bhh;
        p.x[0] = speed; p.x[1] = pos;
        p.x_stride = NOBS * SDIM; p.x_off = t * SDIM; p.x_from_g = 0;
        p.lstm[0] = 0; p.lstm[1] = 1;
        p.inb = t & 1; p.outb = (t + 1) & 1; p.first = (t == 0);
        lstm_step_kernel<<<grid, 256>>>(p);
    }

    combine_kernel<<<1024, 256>>>(speed, pos);

    // ---- Decoders: speed (z=0) and crossing (z=1) ----
    for (int t = 0; t < TOUT; t++) {
        StepP p{};
        p.Wih[0] = dsp_Wih; p.Wih[1] = dcr_Wih;
        p.Whh[0] = dsp_Whh; p.Whh[1] = dcr_Whh;
        p.bih[0] = dsp_bih; p.bih[1] = dcr_bih;
        p.bhh[0] = dsp_bhh; p.bhh[1] = dcr_bhh;
        p.x[0] = nullptr; p.x[1] = nullptr;
        p.x_stride = SDIM; p.x_off = 0; p.x_from_g = 1;
        p.lstm[0] = 2; p.lstm[1] = 3;
        p.inb = t & 1; p.outb = (t + 1) & 1; p.first = 0;
        lstm_step_kernel<<<grid, 256>>>(p);
        head_kernel<<<dim3(BATCH / 8, 2), 256>>>(
            fc_speed_W, fc_speed_b, fc_cross_W, fc_cross_b, emb_W, emb_b,
            out, t, (t + 1) & 1);
    }
}

// round 8
// speedup vs baseline: 2.4590x; 2.4590x over previous
#include <cuda_runtime.h>
#include <cstdint>
#include <math.h>

#define BATCH  16384
#define NOBS   16
#define TOUT   16
#define HPLANE (BATCH * 256)      // 4,194,304 floats per h plane
#define CEL    (BATCH * 256)
#define WPLANE 32768              // [256 k][128 c] floats per (L,slice) weight plane
#define SMEMB  109056             // 2560 + 2*53248

// ---------------- static device scratch ----------------
// h planes: index = (L*2 + pp)*2 + prec  (prec 0=hi, 1=lo), plain [b*256 + j]
__device__ float g_hA[16 * HPLANE];
__device__ float g_c[4 * CEL];
__device__ float g_Wt[32 * WPLANE];       // [(L*8+sp)][k][c] LINEAR (swizzle applied at cp.async dest)
__device__ float g_biasI[32 * 128];
__device__ float g_WihI[32 * 128 * 4];
__device__ float g_hp[2 * CEL];           // plain decoder h for heads
__device__ float g_x[2 * BATCH * 4];      // decoder feedback

// ---------------- helpers ----------------
__device__ __forceinline__ uint32_t smem_u32(const void* p) {
    uint32_t a;
    asm("{ .reg .u64 t; cvta.to.shared.u64 t, %1; cvt.u32.u64 %0, t; }" : "=r"(a) : "l"(p));
    return a;
}
__device__ __forceinline__ float tf32r(float x) {
    uint32_t u;
    asm("cvt.rna.tf32.f32 %0, %1;" : "=r"(u) : "f"(x));
    return __uint_as_float(u);
}
__device__ __forceinline__ void cpasync16(uint32_t dst, const float* src) {
    asm volatile("cp.async.cg.shared.global [%0], [%1], 16;" :: "r"(dst), "l"(src) : "memory");
}
__device__ __forceinline__ void mma8(float* d, uint32_t a0, uint32_t a1, uint32_t a2, uint32_t a3,
                                     uint32_t b0, uint32_t b1) {
    asm volatile("mma.sync.aligned.m16n8k8.row.col.f32.tf32.tf32.f32 "
                 "{%0,%1,%2,%3},{%4,%5,%6,%7},{%8,%9},{%0,%1,%2,%3};"
                 : "+f"(d[0]), "+f"(d[1]), "+f"(d[2]), "+f"(d[3])
                 : "r"(a0), "r"(a1), "r"(a2), "r"(a3), "r"(b0), "r"(b1));
}
__device__ __forceinline__ float sigf(float v) { return __fdividef(1.0f, 1.0f + __expf(-v)); }
__device__ __forceinline__ float tanha(float v) {
    float e = __expf(2.0f * v);
    return 1.0f - __fdividef(2.0f, e + 1.0f);
}

// ---------------- weight prep ----------------
struct WPtr {
    const float* Whh[4]; const float* Wih[4];
    const float* bih[4]; const float* bhh[4];
};

__global__ void prep_weights(WPtr q) {
    int i = blockIdx.x * blockDim.x + threadIdx.x;
    if (i < 1048576) {
        int c  = i & 127;          // c = g*32 + jl
        int k  = (i >> 7) & 255;
        int sp = (i >> 15) & 7;
        int L  = (i >> 18) & 3;
        int row = (c >> 5) * 256 + sp * 32 + (c & 31);
        float v = tf32r(q.Whh[L][row * 256 + k]);
        g_Wt[(size_t)(L * 8 + sp) * WPLANE + k * 128 + c] = v;   // LINEAR store
    }
    if (i < 4096) {
        int c  = i & 127;
        int sp = (i >> 7) & 7;
        int L  = (i >> 10) & 3;
        int row = (c >> 5) * 256 + sp * 32 + (c & 31);
        g_biasI[i] = q.bih[L][row] + q.bhh[L][row];
        #pragma unroll
        for (int s = 0; s < 4; s++) g_WihI[i * 4 + s] = q.Wih[L][row * 4 + s];
    }
}

// ---------------- fused LSTM step ----------------
struct StepP {
    const float* x0; const float* x1;
    int Lbase, inb, outb, first, xsel, xoff;
};

// smem layout (bytes): [0,512) bias, [512,2560) wih, [2560,+2*53248) buffers
// buffer b: Ah @ +0 (128x36 f), Al @ +18432, B @ +36864 (32x128 f, XOR-swizzled)
// staging Gt reuses [2560, 2560+67584)
__global__ __launch_bounds__(256, 2) void lstm_mma_kernel(StepP p) {
    extern __shared__ char smem[];
    const int z = blockIdx.z;
    const int sp = blockIdx.y;
    const int tile = blockIdx.x;
    const int L = p.Lbase + z;
    const int tid = threadIdx.x;
    const int wid = tid >> 5;
    const int lane = tid & 31;
    const int g = lane >> 2;
    const int t = lane & 3;
    const int wm = wid >> 2;
    const int wn = wid & 3;

    float* biasS = (float*)(smem);
    float* wihS  = (float*)(smem + 512);
    if (tid < 128) {
        biasS[tid] = g_biasI[(L * 8 + sp) * 128 + tid];
        ((float4*)wihS)[tid] = ((const float4*)g_WihI)[(L * 8 + sp) * 128 + tid];
    }

    const uint32_t sbase = smem_u32(smem) + 2560;

    float acc[4][4][4];
    #pragma unroll
    for (int mi = 0; mi < 4; mi++)
        #pragma unroll
        for (int ni = 0; ni < 4; ni++)
            #pragma unroll
            for (int e = 0; e < 4; e++) acc[mi][ni][e] = 0.0f;

    if (!p.first) {
        const float* gAh = g_hA + (size_t)((L * 2 + p.inb) * 2) * HPLANE + (size_t)tile * 128 * 256;
        const float* gAl = gAh + HPLANE;
        const float* gB  = g_Wt + (size_t)(L * 8 + sp) * WPLANE;

        // ---- prologue: chunk 0 into buf 0 ----
        {
            uint32_t base = sbase;
            #pragma unroll
            for (int q = 0; q < 4; q++) {
                int ch = tid + q * 256;
                int row = ch >> 3, cg = ch & 7;
                uint32_t d = base + row * 144 + cg * 16;
                cpasync16(d,          gAh + row * 256 + cg * 4);
                cpasync16(d + 18432,  gAl + row * 256 + cg * 4);
            }
            #pragma unroll
            for (int q = 0; q < 4; q++) {
                int ch = tid + q * 256;
                int k = ch >> 5, cg = ch & 31;
                int cgs = cg ^ ((k & 3) << 1);    // swizzle applied HERE only
                cpasync16(base + 36864 + k * 512 + cgs * 16, gB + k * 128 + cg * 4);
            }
            asm volatile("cp.async.commit_group;" ::: "memory");
        }

        for (int c = 0; c < 8; c++) {
            if (c < 7) {
                int cn = c + 1;
                uint32_t base = sbase + (cn & 1) * 53248;
                #pragma unroll
                for (int q = 0; q < 4; q++) {
                    int ch = tid + q * 256;
                    int row = ch >> 3, cg = ch & 7;
                    uint32_t d = base + row * 144 + cg * 16;
                    cpasync16(d,         gAh + row * 256 + cn * 32 + cg * 4);
                    cpasync16(d + 18432, gAl + row * 256 + cn * 32 + cg * 4);
                }
                #pragma unroll
                for (int q = 0; q < 4; q++) {
                    int ch = tid + q * 256;
                    int k = ch >> 5, cg = ch & 31;
                    int cgs = cg ^ ((k & 3) << 1);
                    cpasync16(base + 36864 + k * 512 + cgs * 16,
                              gB + cn * 4096 + k * 128 + cg * 4);
                }
                asm volatile("cp.async.commit_group;" ::: "memory");
                asm volatile("cp.async.wait_group 1;" ::: "memory");
            } else {
                asm volatile("cp.async.wait_group 0;" ::: "memory");
            }
            __syncthreads();

            const char* bb = smem + 2560 + (c & 1) * 53248;
            const float* Ah = (const float*)bb;
            const float* Al = (const float*)(bb + 18432);
            const float* Bs = (const float*)(bb + 36864);

            #pragma unroll
            for (int ks = 0; ks < 4; ks++) {
                int k = ks * 8;
                uint32_t b0[4], b1[4];
                #pragma unroll
                for (int ni = 0; ni < 4; ni++) {
                    int cc = wn * 32 + ni * 8 + g;
                    int cs = cc ^ (t << 3);       // rows k+t and k+t+4 both have (row&3)==t
                    b0[ni] = __float_as_uint(Bs[(k + t) * 128 + cs]);
                    b1[ni] = __float_as_uint(Bs[(k + t + 4) * 128 + cs]);
                }
                #pragma unroll
                for (int mi = 0; mi < 4; mi++) {
                    int r = wm * 64 + mi * 16 + g;
                    uint32_t ah0 = __float_as_uint(Ah[r * 36 + k + t]);
                    uint32_t ah1 = __float_as_uint(Ah[(r + 8) * 36 + k + t]);
                    uint32_t ah2 = __float_as_uint(Ah[r * 36 + k + t + 4]);
                    uint32_t ah3 = __float_as_uint(Ah[(r + 8) * 36 + k + t + 4]);
                    uint32_t al0 = __float_as_uint(Al[r * 36 + k + t]);
                    uint32_t al1 = __float_as_uint(Al[(r + 8) * 36 + k + t]);
                    uint32_t al2 = __float_as_uint(Al[r * 36 + k + t + 4]);
                    uint32_t al3 = __float_as_uint(Al[(r + 8) * 36 + k + t + 4]);
                    #pragma unroll
                    for (int ni = 0; ni < 4; ni++) {
                        mma8(acc[mi][ni], ah0, ah1, ah2, ah3, b0[ni], b1[ni]);
                        mma8(acc[mi][ni], al0, al1, al2, al3, b0[ni], b1[ni]);
                    }
                }
            }
            __syncthreads();
        }

        // ---- stage gates to smem: Gt[row][col], stride 132 ----
        float* Gt = (float*)(smem + 2560);
        #pragma unroll
        for (int mi = 0; mi < 4; mi++) {
            #pragma unroll
            for (int ni = 0; ni < 4; ni++) {
                int r0 = wm * 64 + mi * 16 + g;
                int col = wn * 32 + ni * 8 + t * 2;
                *(float2*)(Gt + r0 * 132 + col)       = make_float2(acc[mi][ni][0], acc[mi][ni][1]);
                *(float2*)(Gt + (r0 + 8) * 132 + col) = make_float2(acc[mi][ni][2], acc[mi][ni][3]);
            }
        }
    }
    __syncthreads();

    // ---- epilogue: thread = (row r, 16 hidden units) ----
    const float* Gt = (const float*)(smem + 2560);
    const int r = tid & 127;
    const int hf = tid >> 7;
    const int jlb = hf * 16;
    const int brow = tile * 128 + r;

    float4 xv;
    if (p.xsel == 0) {
        const float* xp = z ? p.x1 : p.x0;
        xv = ((const float4*)xp)[brow * NOBS + p.xoff];
    } else {
        xv = ((const float4*)g_x)[z * BATCH + brow];
    }

    float* cP  = g_c + (size_t)L * CEL + (size_t)brow * 256 + sp * 32 + jlb;
    float* hHi = g_hA + (size_t)((L * 2 + p.outb) * 2) * HPLANE + (size_t)brow * 256 + sp * 32 + jlb;
    float* hLo = hHi + HPLANE;
    float* hp  = g_hp + (size_t)z * CEL + (size_t)brow * 256 + sp * 32 + jlb;

    #pragma unroll
    for (int q = 0; q < 4; q++) {
        float pre[4][4];   // [gate][j]
        #pragma unroll
        for (int gg = 0; gg < 4; gg++) {
            float4 gv = p.first ? make_float4(0.f, 0.f, 0.f, 0.f)
                                : *(const float4*)(Gt + r * 132 + gg * 32 + jlb + q * 4);
            #pragma unroll
            for (int j = 0; j < 4; j++) {
                int cidx = gg * 32 + jlb + q * 4 + j;
                float v = ((const float*)&gv)[j] + biasS[cidx];
                v += xv.x * wihS[cidx * 4 + 0] + xv.y * wihS[cidx * 4 + 1]
                   + xv.z * wihS[cidx * 4 + 2] + xv.w * wihS[cidx * 4 + 3];
                pre[gg][j] = v;
            }
        }
        float4 cold = p.first ? make_float4(0.f, 0.f, 0.f, 0.f) : ((const float4*)cP)[q];
        float4 cnv, hv, hiv, lov;
        #pragma unroll
        for (int j = 0; j < 4; j++) {
            float ig = sigf(pre[0][j]);
            float fg = sigf(pre[1][j]);
            float gv = tanha(pre[2][j]);
            float og = sigf(pre[3][j]);
            float cn = fg * ((const float*)&cold)[j] + ig * gv;
            float h  = og * tanha(cn);
            float hi = tf32r(h);
            ((float*)&cnv)[j] = cn;
            ((float*)&hv)[j]  = h;
            ((float*)&hiv)[j] = hi;
            ((float*)&lov)[j] = tf32r(h - hi);
        }
        ((float4*)cP)[q] = cnv;
        ((float4*)hHi)[q] = hiv;
        ((float4*)hLo)[q] = lov;
        if (p.Lbase == 2) ((float4*)hp)[q] = hv;
    }
}

// ---------------- combine encoders -> decoder init ----------------
__global__ void combine_kernel(const float* __restrict__ speed, const float* __restrict__ pos) {
    const int stride = gridDim.x * blockDim.x;
    for (int i = blockIdx.x * blockDim.x + threadIdx.x; i < CEL; i += stride) {
        // encoder final pp = 0  -> planes L0: 0,1  L1: 4,5
        float h0 = g_hA[0 * HPLANE + i] + g_hA[1 * HPLANE + i]
                 + g_hA[4 * HPLANE + i] + g_hA[5 * HPLANE + i];
        float hi = tf32r(h0);
        float lo = tf32r(h0 - hi);
        g_hA[8 * HPLANE + i]  = hi;  g_hA[9 * HPLANE + i]  = lo;   // L=2 pp=0
        g_hA[12 * HPLANE + i] = hi;  g_hA[13 * HPLANE + i] = lo;   // L=3 pp=0
        float c0 = g_c[0 * CEL + i] + g_c[1 * CEL + i];
        g_c[2 * CEL + i] = c0;
        g_c[3 * CEL + i] = c0;
    }
    for (int i = blockIdx.x * blockDim.x + threadIdx.x; i < BATCH * 4; i += stride) {
        int b = i >> 2, s = i & 3;
        size_t src = (size_t)b * (NOBS * 4) + (NOBS - 1) * 4 + s;
        g_x[i] = speed[src];
        g_x[BATCH * 4 + i] = pos[src];
    }
}

// ---------------- decoder heads ----------------
__global__ void head_kernel(const float* __restrict__ fcW, const float* __restrict__ fcb,
                            const float* __restrict__ crW, const float* __restrict__ crb,
                            const float* __restrict__ embW, const float* __restrict__ embb,
                            float* __restrict__ out, int t) {
    const int warp = threadIdx.x >> 5;
    const int lane = threadIdx.x & 31;
    const int b = blockIdx.x * 8 + warp;
    const int br = blockIdx.y;
    const float* h = g_hp + (size_t)br * CEL + (size_t)b * 256;

    float hv[8];
    #pragma unroll
    for (int i = 0; i < 8; i++) hv[i] = h[lane + 32 * i];

    if (br == 0) {
        #pragma unroll
        for (int s = 0; s < 4; s++) {
            float v = 0.0f;
            #pragma unroll
            for (int i = 0; i < 8; i++) v += hv[i] * fcW[s * 256 + lane + 32 * i];
            #pragma unroll
            for (int o = 16; o; o >>= 1) v += __shfl_down_sync(0xffffffffu, v, o);
            if (lane == 0) {
                v += fcb[s];
                v = fminf(fmaxf(v, -100.0f), 100.0f);
                out[(size_t)b * (TOUT * 4) + t * 4 + s] = v;
                g_x[b * 4 + s] = v;
            }
        }
    } else {
        float l0 = 0.0f, l1 = 0.0f;
        #pragma unroll
        for (int i = 0; i < 8; i++) {
            l0 += hv[i] * crW[0 * 256 + lane + 32 * i];
            l1 += hv[i] * crW[1 * 256 + lane + 32 * i];
        }
        #pragma unroll
        for (int o = 16; o; o >>= 1) {
            l0 += __shfl_down_sync(0xffffffffu, l0, o);
            l1 += __shfl_down_sync(0xffffffffu, l1, o);
        }
        if (lane == 0) {
            l0 = fmaxf(l0 + crb[0], 0.0f);
            l1 = fmaxf(l1 + crb[1], 0.0f);
            float m = fmaxf(l0, l1);
            float e0 = expf(l0 - m), e1 = expf(l1 - m);
            float inv = 1.0f / (e0 + e1);
            float* outc = out + (size_t)BATCH * TOUT * 4;
            outc[(size_t)b * (TOUT * 2) + t * 2 + 0] = e0 * inv;
            outc[(size_t)b * (TOUT * 2) + t * 2 + 1] = e1 * inv;
        }
        #pragma unroll
        for (int s = 0; s < 4; s++) {
            float v = 0.0f;
            #pragma unroll
            for (int i = 0; i < 8; i++) v += hv[i] * embW[s * 256 + lane + 32 * i];
            #pragma unroll
            for (int o = 16; o; o >>= 1) v += __shfl_down_sync(0xffffffffu, v, o);
            if (lane == 0) g_x[BATCH * 4 + b * 4 + s] = fmaxf(v + embb[s], 0.0f);
        }
    }
}

// ---------------- launch ----------------
extern "C" void kernel_launch(void* const* d_in, const int* in_sizes, int n_in,
                              void* d_out, int out_size) {
    const float* speed      = (const float*)d_in[0];
    const float* pos        = (const float*)d_in[1];
    const float* sp_Wih     = (const float*)d_in[2];
    const float* sp_Whh     = (const float*)d_in[3];
    const float* sp_bih     = (const float*)d_in[4];
    const float* sp_bhh     = (const float*)d_in[5];
    const float* po_Wih     = (const float*)d_in[6];
    const float* po_Whh     = (const float*)d_in[7];
    const float* po_bih     = (const float*)d_in[8];
    const float* po_bhh     = (const float*)d_in[9];
    const float* dsp_Wih    = (const float*)d_in[10];
    const float* dsp_Whh    = (const float*)d_in[11];
    const float* dsp_bih    = (const float*)d_in[12];
    const float* dsp_bhh    = (const float*)d_in[13];
    const float* dcr_Wih    = (const float*)d_in[14];
    const float* dcr_Whh    = (const float*)d_in[15];
    const float* dcr_bih    = (const float*)d_in[16];
    const float* dcr_bhh    = (const float*)d_in[17];
    const float* fc_speed_W = (const float*)d_in[18];
    const float* fc_speed_b = (const float*)d_in[19];
    const float* fc_cross_W = (const float*)d_in[20];
    const float* fc_cross_b = (const float*)d_in[21];
    const float* emb_W      = (const float*)d_in[22];
    const float* emb_b      = (const float*)d_in[23];
    float* out = (float*)d_out;

    cudaFuncSetAttribute(lstm_mma_kernel, cudaFuncAttributeMaxDynamicSharedMemorySize, SMEMB);

    WPtr q;
    q.Whh[0] = sp_Whh;  q.Whh[1] = po_Whh;  q.Whh[2] = dsp_Whh; q.Whh[3] = dcr_Whh;
    q.Wih[0] = sp_Wih;  q.Wih[1] = po_Wih;  q.Wih[2] = dsp_Wih; q.Wih[3] = dcr_Wih;
    q.bih[0] = sp_bih;  q.bih[1] = po_bih;  q.bih[2] = dsp_bih; q.bih[3] = dcr_bih;
    q.bhh[0] = sp_bhh;  q.bhh[1] = po_bhh;  q.bhh[2] = dsp_bhh; q.bhh[3] = dcr_bhh;
    prep_weights<<<4096, 256>>>(q);

    dim3 grid(128, 8, 2);

    for (int t = 0; t < NOBS; t++) {
        StepP p;
        p.x0 = speed; p.x1 = pos;
        p.Lbase = 0; p.inb = t & 1; p.outb = (t + 1) & 1;
        p.first = (t == 0); p.xsel = 0; p.xoff = t;
        lstm_mma_kernel<<<grid, 256, SMEMB>>>(p);
    }

    combine_kernel<<<1024, 256>>>(speed, pos);

    for (int t = 0; t < TOUT; t++) {
        StepP p;
        p.x0 = nullptr; p.x1 = nullptr;
        p.Lbase = 2; p.inb = t & 1; p.outb = (t + 1) & 1;
        p.first = 0; p.xsel = 1; p.xoff = 0;
        lstm_mma_kernel<<<grid, 256, SMEMB>>>(p);
        head_kernel<<<dim3(BATCH / 8, 2), 256>>>(
            fc_speed_W, fc_speed_b, fc_cross_W, fc_cross_b, emb_W, emb_b, out, t);
    }
}